// round 3
// baseline (speedup 1.0000x reference)
#include <cuda_runtime.h>
#include <cuda_bf16.h>
#include <math.h>

#define NN 50000
#define NF 128
#define DIM 10
#define NE 1600000
#define NG 1000
#define PD 12            // padded feature stride (10 -> 12, 3x float4)

// ---------------- scratch (no allocations allowed) ----------------
__device__ int    g_src[NE];
__device__ int    g_dst[NE];
__device__ int    g_deg[NN];
__device__ float  g_deginv[NN];
__device__ float4 g_xl[NN * 3];
__device__ float4 g_xr[NN * 3];
__device__ float4 g_agg1[NN * 3];
__device__ float4 g_agg2[NN * 3];
__device__ float4 g_hl[NN * 3];
__device__ float4 g_hr[NN * 3];
__device__ float4 g_pool[NG * 3];
__device__ int    g_cnt[NG];
__device__ int    g_ei32;   // 1 if edge_index arrived as int32
__device__ int    g_b32;    // 1 if batch arrived as int32

// vector reduction (no return) to global: 1 op moves 16B
__device__ __forceinline__ void red4(float4* p, float4 v) {
    asm volatile("red.global.add.v4.f32 [%0], {%1,%2,%3,%4};"
                 :: "l"(p), "f"(v.x), "f"(v.y), "f"(v.z), "f"(v.w) : "memory");
}

// ---------------- kernels ----------------
__global__ void zero_all() {
    int i = blockIdx.x * blockDim.x + threadIdx.x;
    int stride = gridDim.x * blockDim.x;
    float4 z = make_float4(0.f, 0.f, 0.f, 0.f);
    for (int j = i; j < NN * 3; j += stride) { g_agg1[j] = z; g_agg2[j] = z; }
    for (int j = i; j < NG * 3; j += stride) g_pool[j] = z;
    for (int j = i; j < NN; j += stride) g_deg[j] = 0;
    for (int j = i; j < NG; j += stride) g_cnt[j] = 0;
}

// Detect whether int64-declared inputs actually arrived as int32.
// If data is int32, reading it as int64 pairs two indices -> value >= 2^32
// (node/graph ids are < 50000 / 1000), so out-of-range => int32.
__global__ void detect_dtypes(const long long* ei, const long long* batch) {
    if (blockIdx.x == 0 && threadIdx.x == 0) {
        int f = 0;
        for (int i = 0; i < 64; i++) {
            long long v = ei[i];                 // safe: min buffer is 2*NE*4 bytes
            if (v < 0 || v >= NN) f = 1;
        }
        g_ei32 = f;
        int fb = 0;
        for (int i = 0; i < 64; i++) {
            long long v = batch[12000 + i];      // int64 idx 12000 < NN/2 (safe either way)
            if (v < 0 || v >= NG) fb = 1;
        }
        g_b32 = fb;
    }
}

__global__ void prep_edges(const long long* ei) {
    int e = blockIdx.x * blockDim.x + threadIdx.x;
    if (e >= NE) return;
    int s, d;
    if (g_ei32) {
        const int* e32 = (const int*)ei;
        s = e32[e]; d = e32[NE + e];
    } else {
        s = (int)ei[e]; d = (int)ei[NE + e];
    }
    g_src[e] = s;
    g_dst[e] = d;
    atomicAdd(&g_deg[d], 1);
}

__global__ void node_prep(const long long* batch) {
    int n = blockIdx.x * blockDim.x + threadIdx.x;
    if (n >= NN) return;
    g_deginv[n] = 1.0f / fmaxf((float)g_deg[n], 1.0f);
    int b = g_b32 ? ((const int*)batch)[n] : (int)batch[n];
    atomicAdd(&g_cnt[b], 1);
}

// Fused GEMV: xl = x @ W1_l^T, xr = x @ W1_r^T   ([50000,128] x [128,10] twice)
// 64 nodes per block, smem x-tile with stride-132 skew (conflict-free float4 LDS).
__global__ __launch_bounds__(256) void gemv1(const float* __restrict__ x,
                                             const float* __restrict__ W1l,
                                             const float* __restrict__ W1r) {
    __shared__ __align__(16) float sW[20 * 128];
    __shared__ __align__(16) float sX[64 * 132];
    int t = threadIdx.x;
    for (int i = t; i < 20 * 128; i += 256) {
        int d = i >> 7, k = i & 127;
        sW[i] = (d < 10) ? W1l[d * 128 + k] : W1r[(d - 10) * 128 + k];
    }
    int n0 = blockIdx.x * 64;
    for (int i = t; i < 64 * 32; i += 256) {
        int n = i >> 5, k4 = i & 31;
        int node = n0 + n;
        float4 v = (node < NN) ? ((const float4*)x)[node * 32 + k4]
                               : make_float4(0.f, 0.f, 0.f, 0.f);
        *(float4*)&sX[n * 132 + k4 * 4] = v;
    }
    __syncthreads();
    int n = t & 63, g = t >> 6;     // g in [0,4): 5 outputs each
    int node = n0 + n;
    float acc[5] = {0.f, 0.f, 0.f, 0.f, 0.f};
    const float4* xr4 = (const float4*)&sX[n * 132];
    const float4* w4  = (const float4*)sW;
#pragma unroll
    for (int k4 = 0; k4 < 32; k4++) {
        float4 xv = xr4[k4];
#pragma unroll
        for (int j = 0; j < 5; j++) {
            float4 w = w4[(g * 5 + j) * 32 + k4];
            acc[j] += xv.x * w.x + xv.y * w.y + xv.z * w.z + xv.w * w.w;
        }
    }
    if (node < NN) {
#pragma unroll
        for (int j = 0; j < 5; j++) {
            int d = g * 5 + j;
            float* dst = (d < 10) ? (float*)g_xl : (float*)g_xr;
            int dd = (d < 10) ? d : d - 10;
            dst[node * PD + dd] = acc[j];
        }
    }
}

// Scatter-add: agg[dst] += feat[src].
// PASS 0: g_xl -> g_agg1, PASS 1: g_hl -> g_agg2.
// Device-side symbol references ONLY (host-side __device__ symbol addresses
// are invalid — that was the round-2 bug).
template<int PASS>
__global__ __launch_bounds__(256) void edge_agg() {
    const float4* __restrict__ feat = (PASS == 0) ? g_xl : g_hl;
    float4* agg                     = (PASS == 0) ? g_agg1 : g_agg2;
    int e = blockIdx.x * blockDim.x + threadIdx.x;
    if (e >= NE) return;
    int s = g_src[e], d = g_dst[e];
    float4 a = feat[s * 3 + 0];
    float4 b = feat[s * 3 + 1];
    float4 c = feat[s * 3 + 2];
    red4(&agg[d * 3 + 0], a);
    red4(&agg[d * 3 + 1], b);
    red4(&agg[d * 3 + 2], c);
}

// h1 = relu(agg1*deg_inv + xr); hl = h1 @ W2_l^T; hr = h1 @ W2_r^T
__global__ __launch_bounds__(256) void combine1(const float* __restrict__ W2l,
                                                const float* __restrict__ W2r) {
    __shared__ float sWl[100], sWr[100];
    int t = threadIdx.x;
    if (t < 100) { sWl[t] = W2l[t]; sWr[t] = W2r[t]; }
    __syncthreads();
    int n = blockIdx.x * blockDim.x + t;
    if (n >= NN) return;
    float di = g_deginv[n];
    const float* ag = (const float*)g_agg1 + n * PD;
    const float* xr = (const float*)g_xr + n * PD;
    float h[10];
#pragma unroll
    for (int d = 0; d < 10; d++) h[d] = fmaxf(ag[d] * di + xr[d], 0.f);
    float hl[12], hr[12];
#pragma unroll
    for (int d = 0; d < 10; d++) {
        float al = 0.f, ar = 0.f;
#pragma unroll
        for (int j = 0; j < 10; j++) {
            al += sWl[d * 10 + j] * h[j];
            ar += sWr[d * 10 + j] * h[j];
        }
        hl[d] = al; hr[d] = ar;
    }
    hl[10] = hl[11] = 0.f; hr[10] = hr[11] = 0.f;
    float4* pl = &g_hl[n * 3];
    float4* pr = &g_hr[n * 3];
#pragma unroll
    for (int q = 0; q < 3; q++) {
        pl[q] = make_float4(hl[q*4], hl[q*4+1], hl[q*4+2], hl[q*4+3]);
        pr[q] = make_float4(hr[q*4], hr[q*4+1], hr[q*4+2], hr[q*4+3]);
    }
}

// h2 = agg2*deg_inv + hr; pool[batch[n]] += h2
__global__ void combine2_pool(const long long* batch) {
    int n = blockIdx.x * blockDim.x + threadIdx.x;
    if (n >= NN) return;
    float di = g_deginv[n];
    const float* ag = (const float*)g_agg2 + n * PD;
    const float* hr = (const float*)g_hr + n * PD;
    float h2[12];
#pragma unroll
    for (int d = 0; d < 10; d++) h2[d] = ag[d] * di + hr[d];
    h2[10] = h2[11] = 0.f;
    int b = g_b32 ? ((const int*)batch)[n] : (int)batch[n];
    float4* pp = &g_pool[b * 3];
#pragma unroll
    for (int q = 0; q < 3; q++)
        red4(&pp[q], make_float4(h2[q*4], h2[q*4+1], h2[q*4+2], h2[q*4+3]));
}

__global__ void final_out(const float* __restrict__ Wfc, float* __restrict__ out) {
    int g = blockIdx.x * blockDim.x + threadIdx.x;
    if (g >= NG) return;
    float c = fmaxf((float)g_cnt[g], 1.0f);
    const float* p = (const float*)g_pool + g * PD;
    float z = 0.f;
#pragma unroll
    for (int d = 0; d < 10; d++) z += p[d] * Wfc[d];
    z /= c;
    out[g] = 1.0f / (1.0f + expf(-z));
}

// ---------------- launch ----------------
extern "C" void kernel_launch(void* const* d_in, const int* in_sizes, int n_in,
                              void* d_out, int out_size) {
    // Map inputs by element count (robust to metadata ordering).
    // Equal-size pairs (W1_l/W1_r, W2_l/W2_r) keep declaration order.
    const float *x = 0, *W1l = 0, *W1r = 0, *W2l = 0, *W2r = 0, *Wfc = 0;
    const long long *ei = 0, *batch = 0;
    for (int i = 0; i < n_in; i++) {
        long long sz = in_sizes[i];
        if (sz == (long long)NN * NF)      x = (const float*)d_in[i];
        else if (sz == DIM * NF)           { if (!W1l) W1l = (const float*)d_in[i]; else W1r = (const float*)d_in[i]; }
        else if (sz == DIM * DIM)          { if (!W2l) W2l = (const float*)d_in[i]; else W2r = (const float*)d_in[i]; }
        else if (sz == DIM)                Wfc = (const float*)d_in[i];
        else if (sz == 2LL * NE)           ei = (const long long*)d_in[i];
        else if (sz == NN)                 batch = (const long long*)d_in[i];
    }
    float* out = (float*)d_out;

    const int TB = 256;
    zero_all<<<1024, TB>>>();
    detect_dtypes<<<1, 32>>>(ei, batch);
    prep_edges<<<(NE + TB - 1) / TB, TB>>>(ei);
    node_prep<<<(NN + TB - 1) / TB, TB>>>(batch);
    gemv1<<<(NN + 63) / 64, TB>>>(x, W1l, W1r);
    edge_agg<0><<<(NE + TB - 1) / TB, TB>>>();
    combine1<<<(NN + TB - 1) / TB, TB>>>(W2l, W2r);
    edge_agg<1><<<(NE + TB - 1) / TB, TB>>>();
    combine2_pool<<<(NN + TB - 1) / TB, TB>>>(batch);
    final_out<<<(NG + TB - 1) / TB, TB>>>(Wfc, out);
}